// round 1
// baseline (speedup 1.0000x reference)
#include <cuda_runtime.h>
#include <cuda_bf16.h>

// Global scratch (allocation-free rule: __device__ globals)
__device__ unsigned g_hist_t[32];    // true-element histogram, bins 0..30
__device__ unsigned g_hist_all[32];  // all-element histogram, bins 0..30

// bin = floor(30 * sigmoid(x)), clamped to [0,30]
__device__ __forceinline__ int bin_of(float x) {
    float u   = __expf(-x);                       // FMUL + MUFU.EX2
    float s30 = __fdividef(30.0f, 1.0f + u);      // FADD + MUFU.RCP + FMUL
    int b = (int)s30;                             // s30 >= 0 always
    return b > 30 ? 30 : b;
}

__global__ void zero_kernel() {
    int t = threadIdx.x;
    if (t < 32) { g_hist_t[t] = 0u; g_hist_all[t] = 0u; }
}

// Histogram of ALL elements. Per-lane-replicated shared histogram:
// sh[bin*32 + lane] -> bank == lane -> conflict-free within warp.
__global__ void __launch_bounds__(256) hist_all_kernel(
    const float4* __restrict__ out4, long long n4,
    const float* __restrict__ out, long long total)
{
    __shared__ unsigned sh[32 * 32];
    int tid  = threadIdx.x;
    int lane = tid & 31;
    for (int i = tid; i < 32 * 32; i += blockDim.x) sh[i] = 0u;
    __syncthreads();

    long long stride = (long long)gridDim.x * blockDim.x;
    long long gtid   = (long long)blockIdx.x * blockDim.x + tid;

    for (long long i = gtid; i < n4; i += stride) {
        float4 v = out4[i];
        atomicAdd(&sh[bin_of(v.x) * 32 + lane], 1u);
        atomicAdd(&sh[bin_of(v.y) * 32 + lane], 1u);
        atomicAdd(&sh[bin_of(v.z) * 32 + lane], 1u);
        atomicAdd(&sh[bin_of(v.w) * 32 + lane], 1u);
    }
    // scalar tail (total not multiple of 4)
    for (long long j = n4 * 4 + gtid; j < total; j += stride) {
        atomicAdd(&sh[bin_of(out[j]) * 32 + lane], 1u);
    }
    __syncthreads();

    if (tid < 31) {
        unsigned s = 0;
        #pragma unroll
        for (int l = 0; l < 32; l++) s += sh[tid * 32 + l];
        atomicAdd(&g_hist_all[tid], s);
    }
}

// Histogram of the 500K "true" elements: gather output[n*C + target[n]]
__global__ void __launch_bounds__(256) hist_t_kernel(
    const float* __restrict__ out, const int* __restrict__ tg,
    int N, int C)
{
    __shared__ unsigned sht[32];
    int tid = threadIdx.x;
    if (tid < 32) sht[tid] = 0u;
    __syncthreads();

    long long stride = (long long)gridDim.x * blockDim.x;
    for (long long n = (long long)blockIdx.x * blockDim.x + tid; n < N; n += stride) {
        int t = tg[n];
        float x = __ldg(out + n * (long long)C + t);
        atomicAdd(&sht[bin_of(x)], 1u);
    }
    __syncthreads();
    if (tid < 31) atomicAdd(&g_hist_t[tid], sht[tid]);
}

// Single-thread epilogue: cumsums, reverse, trapezoid area.
__global__ void finalize_kernel(float* __restrict__ out, double trues_sum, double total)
{
    if (threadIdx.x != 0 || blockIdx.x != 0) return;
    const double EPS = 1e-8;
    double falses_sum = total - trues_sum;

    // tp_asc[k] = trues - cumsum(hist_t)[k], fp_asc[k] = falses - cumsum(hist_f)[k], k=0..29
    double tp_asc[30], fp_asc[30];
    double cum_t = 0.0, cum_a = 0.0;
    for (int k = 0; k < 30; k++) {
        cum_t += (double)g_hist_t[k];
        cum_a += (double)g_hist_all[k];
        tp_asc[k] = trues_sum - cum_t;
        fp_asc[k] = falses_sum - (cum_a - cum_t);
    }
    // tprs/fprs: index 0 is 0, index j (1..30) is reversed (descending-threshold) rates
    double area = 0.0;
    double prev_tpr = 0.0, prev_fpr = 0.0;
    double inv_t = 1.0 / (trues_sum + EPS);
    double inv_f = 1.0 / (falses_sum + EPS);
    for (int j = 1; j <= 30; j++) {
        double tpr = tp_asc[30 - j] * inv_t;
        double fpr = fp_asc[30 - j] * inv_f;
        double w = fabs(fpr - prev_fpr);
        area += w * 0.5 * (tpr + prev_tpr);
        prev_tpr = tpr; prev_fpr = fpr;
    }
    out[0] = (float)area;
}

extern "C" void kernel_launch(void* const* d_in, const int* in_sizes, int n_in,
                              void* d_out, int out_size)
{
    const float* output = (const float*)d_in[0];
    const int*   target = (const int*)d_in[1];
    long long total = (long long)in_sizes[0];
    int N = in_sizes[1];
    int C = (int)(total / N);
    long long n4 = total / 4;

    zero_kernel<<<1, 32>>>();

    int blocksA = 1184;  // 148 SMs * 8
    hist_all_kernel<<<blocksA, 256>>>((const float4*)output, n4, output, total);

    int blocksT = (N + 255) / 256;
    if (blocksT > 2048) blocksT = 2048;
    hist_t_kernel<<<blocksT, 256>>>(output, target, N, C);

    finalize_kernel<<<1, 1>>>((float*)d_out, (double)N, (double)total);
}